// round 6
// baseline (speedup 1.0000x reference)
#include <cuda_runtime.h>
#include <cuda_bf16.h>

// Problem constants (fixed shapes from reference setup_inputs)
#define B_   2
#define K_   64
#define N_   16
#define HWF  (128*128)
#define H_   128
#define W_   128
#define ROWS 32                     // rows per block
#define NBLK (B_*K_*4)              // 512 blocks, 4 per (b,k)
#define NPIX ((double)(B_*K_*H_*W_))
#define LOG_EPS  (-27.631021115928547f)   /* logf(1e-12) */

__device__ double       g_partial[NBLK];
__device__ unsigned int g_ticket = 0u;

__device__ __forceinline__ unsigned long long f32x2_mul(unsigned long long a,
                                                        unsigned long long b)
{
    unsigned long long d;
    asm("mul.rn.f32x2 %0, %1, %2;" : "=l"(d) : "l"(a), "l"(b));
    return d;
}
__device__ __forceinline__ unsigned long long f32x2_fma(unsigned long long a,
                                                        unsigned long long b,
                                                        unsigned long long c)
{
    unsigned long long d;
    asm("fma.rn.f32x2 %0, %1, %2, %3;" : "=l"(d) : "l"(a), "l"(b), "l"(c));
    return d;
}
__device__ __forceinline__ float f32x2_hadd(unsigned long long v)
{
    unsigned int lo, hi;
    asm("mov.b64 {%0, %1}, %2;" : "=r"(lo), "=r"(hi) : "l"(v));
    return __uint_as_float(lo) + __uint_as_float(hi);
}

__global__ __launch_bounds__(256)
void gauss_fused(const float* __restrict__ centers,
                 const float* __restrict__ radius,
                 const float* __restrict__ mask,
                 const int* __restrict__ ind32,     // raw ind buffer, dtype sniffed
                 const float* __restrict__ target,
                 const float* __restrict__ peak,
                 float* __restrict__ out, int out_size)
{
    __shared__ float  s_tgt[ROWS][W_];      // 16KB  target slab (cp.async)
    __shared__ float4 s_Ex[W_][N_/4];       // 8KB   Ex[w][n]   (positive exps)
    __shared__ float4 s_Ey[ROWS][N_/4];     // 2KB   -Ey[hl][n] (NEGATED exps)
    __shared__ float  s_pxy[2*N_];
    __shared__ float  s_negInv, s_m, s_logm;
    __shared__ float  s_warp[8];
    __shared__ int    s_idx;
    __shared__ int    s_last;

    const int bid     = blockIdx.x;
    const int pair    = bid >> 2;           // (b,k) index == b*K + k
    const int rowbase = (bid & 3) * ROWS;
    const int b   = pair >> 6;
    const int k   = pair & 63;
    const int tid = threadIdx.x;

    // ---- kick off async target prefetch immediately (hidden behind phases A/B) ----
    {
        unsigned int sbase =
            (unsigned int)__cvta_generic_to_shared(&s_tgt[0][0]);
        const float* g = target + ((size_t)pair*H_ + rowbase)*W_;
        #pragma unroll
        for (int c = 0; c < 4; c++) {
            int chunk = c*256 + tid;                 // 1024 x 16B = 16KB
            asm volatile("cp.async.cg.shared.global [%0], [%1], 16;"
                         :: "r"(sbase + chunk*16), "l"(g + chunk*4));
        }
        asm volatile("cp.async.commit_group;");
    }

    // ---- dtype sniff for ind: int64 vs int32 (reads stay in first 256B) ----
    if (tid < 32) {
        int lo = ind32[2*tid];
        int hi = ind32[2*tid + 1];
        unsigned ok = __ballot_sync(0xffffffffu,
                                    hi == 0 && (unsigned)lo < (unsigned)HWF);
        if (tid == 0) {
            int e = pair;
            int idx = (ok == 0xffffffffu) ? ind32[2*e]   // int64 (low word)
                                          : ind32[e];    // int32
            s_idx = min(max(idx, 0), HWF - 1);
        }
    }
    __syncthreads();
    const int idx = s_idx;

    // ---- Phase A: gather centers/radius/mask ----
    if (tid < 2*N_) {
        float v = centers[(b*2*N_ + tid)*HWF + idx];
        s_pxy[tid] = v + peak[pair*2 + (tid & 1)];
    }
    if (tid == 32) {
        float r  = radius[b*HWF + idx];
        s_negInv = -0.5f / (r*r);
        float m  = mask[b*K_ + k];
        s_m      = m;
        s_logm   = __logf(fmaxf(m, 1e-38f));
    }
    __syncthreads();

    // ---- Phase B: separable exp tables (Ey stored NEGATED) ----
    // Ex: 2048 entries, Ey: 512 entries -> 2560 = 10*256
    {
        const float negInv = s_negInv;
        #pragma unroll
        for (int i = 0; i < 10; i++) {
            int e = i*256 + tid;            // 0..2559
            int n = e & 15;
            int v = e >> 4;                 // 0..159
            if (v < 128) {
                float d = s_pxy[2*n] - (float)v;
                ((float*)s_Ex)[v*16 + n] = __expf(d*d*negInv);
            } else {
                int hl = v - 128;           // 0..31
                float d = s_pxy[2*n + 1] - (float)(hl + rowbase);
                ((float*)s_Ey)[hl*16 + n] = -__expf(d*d*negInv);
            }
        }
    }
    asm volatile("cp.async.wait_group 0;");
    __syncthreads();

    // ---- Phase C: per-pixel loss (packed f32x2 dot yields -g directly) ----
    const int   w0   = tid & 127;
    const int   rg   = tid >> 7;            // 2 row groups
    const float m    = s_m;
    const float logm = s_logm;
    const float one_minus_m = 1.0f - m;

    // this thread's Ex column as 8 packed f32x2 values, kept in registers
    unsigned long long ex[8];
    {
        const ulonglong2* exp_ = (const ulonglong2*)&s_Ex[w0][0];
        #pragma unroll
        for (int j = 0; j < 4; j++) {
            ulonglong2 v = exp_[j];
            ex[2*j]   = v.x;
            ex[2*j+1] = v.y;
        }
    }

    float acc = 0.0f;
    #pragma unroll
    for (int it = 0; it < 16; it++) {
        int hl = 2*it + rg;                 // local row (broadcast LDS in warp)
        const ulonglong2* eyp = (const ulonglong2*)&s_Ey[hl][0];
        ulonglong2 e0 = eyp[0];
        ulonglong2 e1 = eyp[1];
        ulonglong2 e2 = eyp[2];
        ulonglong2 e3 = eyp[3];

        unsigned long long a2 = f32x2_mul(ex[0], e0.x);
        a2 = f32x2_fma(ex[1], e0.y, a2);
        a2 = f32x2_fma(ex[2], e1.x, a2);
        a2 = f32x2_fma(ex[3], e1.y, a2);
        a2 = f32x2_fma(ex[4], e2.x, a2);
        a2 = f32x2_fma(ex[5], e2.y, a2);
        a2 = f32x2_fma(ex[6], e3.x, a2);
        a2 = f32x2_fma(ex[7], e3.y, a2);
        float ng = f32x2_hadd(a2);          // = -g  (Ey negated)

        // p = m*sigmoid(g), t = m*target;  e = exp(-g)
        // log p     = log m - log(1+e)
        // log (1-p) = log((1-m)+e) - log(1+e)
        float e  = __expf(ng);
        float L1 = __logf(1.0f + e);
        float lp  = fmaxf(logm - L1,                    LOG_EPS);
        float l1p = fmaxf(__logf(one_minus_m + e) - L1, LOG_EPS);

        float t = m * s_tgt[hl][w0];
        acc -= fmaf(t, lp - l1p, l1p);      // -(t*lp + (1-t)*l1p)
    }

    // ---- block reduction (deterministic tree) ----
    #pragma unroll
    for (int o = 16; o; o >>= 1)
        acc += __shfl_down_sync(0xffffffffu, acc, o);
    if ((tid & 31) == 0) s_warp[tid >> 5] = acc;
    __syncthreads();
    if (tid == 0) {
        double s = 0.0;
        #pragma unroll
        for (int i = 0; i < 8; i++) s += (double)s_warp[i];
        g_partial[bid] = s;
        __threadfence();
        unsigned int v = atomicAdd(&g_ticket, 1u);
        s_last = (v == NBLK - 1u) ? 1 : 0;
    }
    __syncthreads();

    // ---- last block: deterministic final tree + output ----
    if (s_last) {
        __shared__ double sh[256];
        sh[tid] = g_partial[tid] + g_partial[tid + 256];
        __syncthreads();
        #pragma unroll
        for (int o = 128; o; o >>= 1) {
            if (tid < o) sh[tid] += sh[tid + o];
            __syncthreads();
        }
        float loss = (float)(sh[0] / NPIX);
        for (int i = tid; i < out_size; i += 256) out[i] = loss;
        if (tid == 0) g_ticket = 0u;        // reset for next graph replay
    }
}

extern "C" void kernel_launch(void* const* d_in, const int* in_sizes, int n_in,
                              void* d_out, int out_size)
{
    const float* centers = (const float*)d_in[0];
    const float* radius  = (const float*)d_in[1];
    const float* mask    = (const float*)d_in[2];
    const int*   ind32   = (const int*)d_in[3];
    const float* target  = (const float*)d_in[4];
    const float* peak    = (const float*)d_in[5];

    gauss_fused<<<NBLK, 256>>>(centers, radius, mask, ind32, target, peak,
                               (float*)d_out, out_size);
}

// round 7
// speedup vs baseline: 1.6842x; 1.6842x over previous
#include <cuda_runtime.h>
#include <cuda_bf16.h>

// Problem constants (fixed shapes from reference setup_inputs)
#define B_   2
#define K_   64
#define N_   16
#define HWF  (128*128)
#define H_   128
#define W_   128
#define ROWS 64                     // rows per block
#define NBLK (B_*K_*2)              // 256 blocks, 2 per (b,k)
#define NPIX ((double)(B_*K_*H_*W_))
#define LOG2_EPS   (-39.863137138648348f)   /* log2(1e-12) */
#define NEG_LOG2E  (-1.4426950408889634f)
#define LN2        (0.6931471805599453)

__device__ double       g_partial[NBLK];
__device__ unsigned int g_ticket = 0u;

__device__ __forceinline__ unsigned long long f32x2_mul(unsigned long long a,
                                                        unsigned long long b)
{
    unsigned long long d;
    asm("mul.rn.f32x2 %0, %1, %2;" : "=l"(d) : "l"(a), "l"(b));
    return d;
}
__device__ __forceinline__ unsigned long long f32x2_fma(unsigned long long a,
                                                        unsigned long long b,
                                                        unsigned long long c)
{
    unsigned long long d;
    asm("fma.rn.f32x2 %0, %1, %2, %3;" : "=l"(d) : "l"(a), "l"(b), "l"(c));
    return d;
}
__device__ __forceinline__ float f32x2_hadd(unsigned long long v)
{
    unsigned int lo, hi;
    asm("mov.b64 {%0, %1}, %2;" : "=r"(lo), "=r"(hi) : "l"(v));
    return __uint_as_float(lo) + __uint_as_float(hi);
}
__device__ __forceinline__ float ex2f(float x)
{ float y; asm("ex2.approx.ftz.f32 %0, %1;" : "=f"(y) : "f"(x)); return y; }
__device__ __forceinline__ float lg2f(float x)
{ float y; asm("lg2.approx.ftz.f32 %0, %1;" : "=f"(y) : "f"(x)); return y; }

__global__ __launch_bounds__(256)
void gauss_fused(const float* __restrict__ centers,
                 const float* __restrict__ radius,
                 const float* __restrict__ mask,
                 const int* __restrict__ ind32,     // raw ind buffer, dtype sniffed
                 const float* __restrict__ target,
                 const float* __restrict__ peak,
                 float* __restrict__ out, int out_size)
{
    __shared__ float  s_tgt[ROWS][W_];      // 32KB target slab (cp.async)
    __shared__ float4 s_Ex[W_][N_/4];       // 8KB  Ex[w][n]            (plain exps)
    __shared__ float4 s_Ey[ROWS][N_/4];     // 4KB  -log2e*Ey[hl][n]    (folded)
    __shared__ float  s_pxy[2*N_];
    __shared__ float  s_negInv, s_m, s_logm2;
    __shared__ float  s_warp[8];
    __shared__ int    s_idx;
    __shared__ int    s_last;

    const int bid     = blockIdx.x;
    const int pair    = bid >> 1;           // (b,k) index == b*K + k
    const int rowbase = (bid & 1) * ROWS;
    const int b   = pair >> 6;
    const int k   = pair & 63;
    const int tid = threadIdx.x;

    // ---- kick off async target prefetch immediately (hidden behind A/B) ----
    {
        unsigned int sbase = (unsigned int)__cvta_generic_to_shared(&s_tgt[0][0]);
        const float* g = target + ((size_t)pair*H_ + rowbase)*W_;
        #pragma unroll
        for (int c = 0; c < 8; c++) {
            int chunk = c*256 + tid;                 // 2048 x 16B = 32KB
            asm volatile("cp.async.cg.shared.global [%0], [%1], 16;"
                         :: "r"(sbase + chunk*16), "l"(g + chunk*4));
        }
        asm volatile("cp.async.commit_group;");
    }

    // ---- dtype sniff for ind: int64 vs int32 (reads stay in first 256B) ----
    if (tid < 32) {
        int lo = ind32[2*tid];
        int hi = ind32[2*tid + 1];
        unsigned ok = __ballot_sync(0xffffffffu,
                                    hi == 0 && (unsigned)lo < (unsigned)HWF);
        if (tid == 0) {
            int e = pair;
            int idx = (ok == 0xffffffffu) ? ind32[2*e]   // int64 (low word)
                                          : ind32[e];    // int32
            s_idx = min(max(idx, 0), HWF - 1);
        }
    }
    __syncthreads();
    const int idx = s_idx;

    // ---- Phase A: gather centers/radius/mask ----
    if (tid < 2*N_) {
        float v = centers[(b*2*N_ + tid)*HWF + idx];
        s_pxy[tid] = v + peak[pair*2 + (tid & 1)];
    }
    if (tid == 32) {
        float r   = radius[b*HWF + idx];
        s_negInv  = -0.5f / (r*r);
        float m   = mask[b*K_ + k];
        s_m       = m;
        s_logm2   = lg2f(fmaxf(m, 1e-38f));
    }
    __syncthreads();

    // ---- Phase B: separable exp tables (Ey folded with -log2e) ----
    // Ex: 2048 entries, Ey: 1024 entries -> 3072 = 12*256
    {
        const float negInv = s_negInv;
        #pragma unroll
        for (int i = 0; i < 12; i++) {
            int e = i*256 + tid;            // 0..3071
            int n = e & 15;
            int v = e >> 4;                 // 0..191
            if (v < 128) {
                float d = s_pxy[2*n] - (float)v;
                ((float*)s_Ex)[v*16 + n] = __expf(d*d*negInv);
            } else {
                int hl = v - 128;           // 0..63
                float d = s_pxy[2*n + 1] - (float)(hl + rowbase);
                ((float*)s_Ey)[hl*16 + n] = NEG_LOG2E * __expf(d*d*negInv);
            }
        }
    }
    asm volatile("cp.async.wait_group 0;");
    __syncthreads();

    // ---- Phase C: per-pixel loss, 2 rows per iteration (dual chains) ----
    const int   w0    = tid & 127;
    const int   rg    = tid >> 7;           // 2 row groups
    const float m     = s_m;
    const float logm2 = s_logm2;
    const float one_minus_m = 1.0f - m;

    // this thread's Ex column as 8 packed f32x2 values, kept in registers
    unsigned long long ex[8];
    {
        const ulonglong2* exp_ = (const ulonglong2*)&s_Ex[w0][0];
        #pragma unroll
        for (int j = 0; j < 4; j++) {
            ulonglong2 v = exp_[j];
            ex[2*j]   = v.x;
            ex[2*j+1] = v.y;
        }
    }

    float acc = 0.0f;                       // BCE sum in log2 units (negated)
    #pragma unroll
    for (int it = 0; it < 16; it++) {
        const int ha = 4*it + rg;           // rows: 4it+rg and 4it+2+rg
        const int hb = ha + 2;

        const ulonglong2* eyA = (const ulonglong2*)&s_Ey[ha][0];
        const ulonglong2* eyB = (const ulonglong2*)&s_Ey[hb][0];
        ulonglong2 a0 = eyA[0], a1 = eyA[1], a2v = eyA[2], a3 = eyA[3];
        ulonglong2 b0 = eyB[0], b1 = eyB[1], b2v = eyB[2], b3 = eyB[3];

        unsigned long long dA = f32x2_mul(ex[0], a0.x);
        unsigned long long dB = f32x2_mul(ex[0], b0.x);
        dA = f32x2_fma(ex[1], a0.y, dA);  dB = f32x2_fma(ex[1], b0.y, dB);
        dA = f32x2_fma(ex[2], a1.x, dA);  dB = f32x2_fma(ex[2], b1.x, dB);
        dA = f32x2_fma(ex[3], a1.y, dA);  dB = f32x2_fma(ex[3], b1.y, dB);
        dA = f32x2_fma(ex[4], a2v.x, dA); dB = f32x2_fma(ex[4], b2v.x, dB);
        dA = f32x2_fma(ex[5], a2v.y, dA); dB = f32x2_fma(ex[5], b2v.y, dB);
        dA = f32x2_fma(ex[6], a3.x, dA);  dB = f32x2_fma(ex[6], b3.x, dB);
        dA = f32x2_fma(ex[7], a3.y, dA);  dB = f32x2_fma(ex[7], b3.y, dB);
        float ngA = f32x2_hadd(dA);         // = log2(exp(-gA))
        float ngB = f32x2_hadd(dB);

        // e = exp(-g);  P = log2(1+e);  Q = log2((1-m)+e)
        // log2 p     = log2 m - P
        // log2 (1-p) = Q - P
        float eA = ex2f(ngA);
        float eB = ex2f(ngB);
        float PA = lg2f(1.0f + eA);
        float PB = lg2f(1.0f + eB);
        float QA = lg2f(one_minus_m + eA);
        float QB = lg2f(one_minus_m + eB);

        float lpA  = fmaxf(logm2 - PA, LOG2_EPS);
        float lpB  = fmaxf(logm2 - PB, LOG2_EPS);
        float l1pA = fmaxf(QA - PA,    LOG2_EPS);
        float l1pB = fmaxf(QB - PB,    LOG2_EPS);

        float tA = m * s_tgt[ha][w0];
        float tB = m * s_tgt[hb][w0];
        acc -= fmaf(tA, lpA - l1pA, l1pA);
        acc -= fmaf(tB, lpB - l1pB, l1pB);
    }

    // ---- block reduction (deterministic tree) ----
    #pragma unroll
    for (int o = 16; o; o >>= 1)
        acc += __shfl_down_sync(0xffffffffu, acc, o);
    if ((tid & 31) == 0) s_warp[tid >> 5] = acc;
    __syncthreads();
    if (tid == 0) {
        double s = 0.0;
        #pragma unroll
        for (int i = 0; i < 8; i++) s += (double)s_warp[i];
        g_partial[bid] = s;
        __threadfence();
        unsigned int v = atomicAdd(&g_ticket, 1u);
        s_last = (v == NBLK - 1u) ? 1 : 0;
    }
    __syncthreads();

    // ---- last block: deterministic final tree + output ----
    if (s_last) {
        __shared__ double sh[NBLK];
        sh[tid] = g_partial[tid];
        __syncthreads();
        #pragma unroll
        for (int o = 128; o; o >>= 1) {
            if (tid < o) sh[tid] += sh[tid + o];
            __syncthreads();
        }
        float loss = (float)(sh[0] * LN2 / NPIX);   // back to natural log units
        for (int i = tid; i < out_size; i += 256) out[i] = loss;
        if (tid == 0) g_ticket = 0u;        // reset for next graph replay
    }
}

extern "C" void kernel_launch(void* const* d_in, const int* in_sizes, int n_in,
                              void* d_out, int out_size)
{
    const float* centers = (const float*)d_in[0];
    const float* radius  = (const float*)d_in[1];
    const float* mask    = (const float*)d_in[2];
    const int*   ind32   = (const int*)d_in[3];
    const float* target  = (const float*)d_in[4];
    const float* peak    = (const float*)d_in[5];

    gauss_fused<<<NBLK, 256>>>(centers, radius, mask, ind32, target, peak,
                               (float*)d_out, out_size);
}